// round 14
// baseline (speedup 1.0000x reference)
#include <cuda_runtime.h>
#include <math.h>
#include <stdint.h>

#define D_MODEL 2048
#define SEQ     2048
#define NBATCH  2
#define NH      32
#define NKV     8
#define HD      64
#define NREP    4
#define KVW     (NKV*HD)        // 512
#define MROWS   (NBATCH*SEQ)    // 4096

// scratch (static device globals — no allocations allowed)
__device__ float g_q[(size_t)MROWS * D_MODEL];
__device__ float g_k[(size_t)MROWS * KVW];
__device__ float g_v[(size_t)MROWS * KVW];
__device__ float g_attn[(size_t)MROWS * D_MODEL];

__device__ __forceinline__ uint32_t f2tf32(float x) {
    uint32_t r;
    asm("cvt.rna.tf32.f32 %0, %1;" : "=r"(r) : "f"(x));
    return r;
}

#define MMA_TF32(C, A, B)                                                     \
    asm volatile(                                                             \
        "mma.sync.aligned.m16n8k8.row.col.f32.tf32.tf32.f32 "                \
        "{%0,%1,%2,%3}, {%4,%5,%6,%7}, {%8,%9}, {%0,%1,%2,%3};"              \
        : "+f"((C)[0]), "+f"((C)[1]), "+f"((C)[2]), "+f"((C)[3])             \
        : "r"((A)[0]), "r"((A)[1]), "r"((A)[2]), "r"((A)[3]),                \
          "r"((B)[0]), "r"((B)[1]))

__device__ __forceinline__ void cp_async16(uint32_t* smem_dst, const float* gsrc) {
    uint32_t s = (uint32_t)__cvta_generic_to_shared(smem_dst);
    asm volatile("cp.async.cg.shared.global [%0], [%1], 16;\n"
                 :: "r"(s), "l"(gsrc));
}
#define CP_COMMIT() asm volatile("cp.async.commit_group;\n")
#define CP_WAIT1()  asm volatile("cp.async.wait_group 1;\n")

// ---------------------------------------------------------------------------
// Pipelined tf32 GEMM core: 3-stage cp.async, BK=16, ONE sync per iteration.
// C[128][128 block] = Ab[128][K] @ Bb[128][K]^T, 256 thr, 8 warps (2m x 4n).
// smem raw fp32 [3][128][20] per matrix; cvt.rna at frag load (same rounding).
// ---------------------------------------------------------------------------
#define GP_STRIDE 20
#define GP_STAGE  (128*GP_STRIDE)
#define GP_NSTG   3
#define GP_SMEM   (GP_NSTG*GP_STAGE*2*4)     // 61440 bytes

__device__ __forceinline__ void gemm_core(
    const float* __restrict__ Ab, const float* __restrict__ Bb,
    float* __restrict__ C, int N, int cx, int cy, int K)
{
    extern __shared__ uint32_t smp[];
    uint32_t* As = smp;                        // [3][128][20]
    uint32_t* Bs = smp + GP_NSTG*GP_STAGE;

    const int tid  = threadIdx.x;
    const int lane = tid & 31, warp = tid >> 5;
    const int wm = (warp & 1) * 64, wn = (warp >> 1) * 32;
    const int lr = lane >> 2,  lc = lane & 3;

    float acc[4][4][4];
    #pragma unroll
    for (int mt = 0; mt < 4; mt++)
        #pragma unroll
        for (int nt = 0; nt < 4; nt++)
            #pragma unroll
            for (int e = 0; e < 4; e++) acc[mt][nt][e] = 0.f;

    // tile = 16 k-columns = 4 float4 chunks/row; rows 0..127, 2 chunks/thread
    const int r_ld  = (tid + 0)   >> 2;        // 0..63
    const int r_ld2 = (tid + 256) >> 2;        // 64..127
    const int kc_ld  = (tid & 3) * 4;          // 0,4,8,12

    #define GP_ISSUE(tile, stage)                                             \
        do {                                                                  \
            cp_async16(As + (stage)*GP_STAGE + r_ld *GP_STRIDE + kc_ld,       \
                       Ab + (size_t)r_ld *K + (tile)*16 + kc_ld);             \
            cp_async16(As + (stage)*GP_STAGE + r_ld2*GP_STRIDE + kc_ld,       \
                       Ab + (size_t)r_ld2*K + (tile)*16 + kc_ld);             \
            cp_async16(Bs + (stage)*GP_STAGE + r_ld *GP_STRIDE + kc_ld,       \
                       Bb + (size_t)r_ld *K + (tile)*16 + kc_ld);             \
            cp_async16(Bs + (stage)*GP_STAGE + r_ld2*GP_STRIDE + kc_ld,       \
                       Bb + (size_t)r_ld2*K + (tile)*16 + kc_ld);             \
        } while (0)

    GP_ISSUE(0, 0); CP_COMMIT();
    GP_ISSUE(1, 1); CP_COMMIT();

    const int niter = K / 16;
    int stage = 0;
    for (int it = 0; it < niter; it++) {
        CP_WAIT1();                // tile `it` landed (<=1 group outstanding)
        __syncthreads();           // collective readiness + protects stage it-1

        const float* Ac = (const float*)(As + stage*GP_STAGE);
        const float* Bc = (const float*)(Bs + stage*GP_STAGE);

        #pragma unroll
        for (int ks = 0; ks < 2; ks++) {
            const int kb = ks * 8;
            uint32_t af[4][4], bf[4][2];
            #pragma unroll
            for (int mt = 0; mt < 4; mt++) {
                int r0 = wm + mt*16 + lr;
                af[mt][0] = f2tf32(Ac[(r0    )*GP_STRIDE + kb + lc]);
                af[mt][1] = f2tf32(Ac[(r0 + 8)*GP_STRIDE + kb + lc]);
                af[mt][2] = f2tf32(Ac[(r0    )*GP_STRIDE + kb + lc + 4]);
                af[mt][3] = f2tf32(Ac[(r0 + 8)*GP_STRIDE + kb + lc + 4]);
            }
            #pragma unroll
            for (int nt = 0; nt < 4; nt++) {
                int n0 = wn + nt*8 + lr;
                bf[nt][0] = f2tf32(Bc[n0*GP_STRIDE + kb + lc]);
                bf[nt][1] = f2tf32(Bc[n0*GP_STRIDE + kb + lc + 4]);
            }
            #pragma unroll
            for (int mt = 0; mt < 4; mt++)
                #pragma unroll
                for (int nt = 0; nt < 4; nt++)
                    MMA_TF32(acc[mt][nt], af[mt], bf[nt]);
        }

        if (it + 2 < niter) {
            int st2 = stage + 2; if (st2 >= 3) st2 -= 3;
            GP_ISSUE(it + 2, st2);
        }
        CP_COMMIT();
        stage = (stage == 2) ? 0 : stage + 1;
    }

    #pragma unroll
    for (int mt = 0; mt < 4; mt++) {
        int r0 = cy + wm + mt*16 + lr;
        #pragma unroll
        for (int nt = 0; nt < 4; nt++) {
            int cc = cx + wn + nt*8 + lc*2;
            *(float2*)(C + (size_t)r0 * N + cc) =
                make_float2(acc[mt][nt][0], acc[mt][nt][1]);
            *(float2*)(C + (size_t)(r0 + 8) * N + cc) =
                make_float2(acc[mt][nt][2], acc[mt][nt][3]);
        }
    }
    #undef GP_ISSUE
}

// Fused q/k/v projections: grid (24, MROWS/128).  bx<16 -> q, <20 -> k, else v
__global__ __launch_bounds__(256, 2)
void gemm_qkv(const float* __restrict__ x,
              const float* __restrict__ wq, const float* __restrict__ wk,
              const float* __restrict__ wv,
              float* __restrict__ q, float* __restrict__ k, float* __restrict__ v)
{
    const int bx = blockIdx.x, by = blockIdx.y;
    const float* Ab = x + (size_t)by * 128 * D_MODEL;
    const float* Bb; float* C; int N, cx;
    if (bx < 16)      { Bb = wq + (size_t)bx*128*D_MODEL;      C = q; N = D_MODEL; cx = bx*128; }
    else if (bx < 20) { Bb = wk + (size_t)(bx-16)*128*D_MODEL; C = k; N = KVW;     cx = (bx-16)*128; }
    else              { Bb = wv + (size_t)(bx-20)*128*D_MODEL; C = v; N = KVW;     cx = (bx-20)*128; }
    gemm_core(Ab, Bb, C, N, cx, by*128, D_MODEL);
}

// Plain pipelined GEMM: C[M,N] = A[M,K] @ B[N,K]^T
__global__ __launch_bounds__(256, 2)
void gemm_tf32p(const float* __restrict__ A, const float* __restrict__ B,
                float* __restrict__ C, int N, int K)
{
    gemm_core(A + (size_t)blockIdx.y*128*K, B + (size_t)blockIdx.x*128*K,
              C, N, blockIdx.x*128, blockIdx.y*128, K);
}

// ---------------------------------------------------------------------------
// SIGN-FLIPPED interleaved RoPE (rotation by -theta), in-place.  [VERIFIED]
// ---------------------------------------------------------------------------
__global__ void rope_kernel(float* __restrict__ buf, int width)
{
    int idx = blockIdx.x * blockDim.x + threadIdx.x;
    int ppr = width >> 1;
    if (idx >= MROWS * ppr) return;
    int m = idx / ppr;
    int p = idx - m * ppr;
    int i = p & 31;
    int s = m & (SEQ - 1);
    float inv = powf(10000.0f, -((float)(2*i)) / 64.0f);
    float ang = (float)s * inv;
    float c, sn;
    sincosf(ang, &c, &sn);
    sn = -sn;
    float* el = buf + (size_t)m * width + 2*p;
    float xr = el[0], xi = el[1];
    el[0] = xr * c - xi * sn;
    el[1] = xr * sn + xi * c;
}

// ---------------------------------------------------------------------------
// Tensor-core flash attention (tf32 MMA), causal, GQA.
// 2 CTAs/SM, descending-qt launch order, uint4 (STS.128) tile loads.
// ---------------------------------------------------------------------------
#define FM_QS 68
#define FM_KS 68
#define FM_VS 72
#define FM_SMEM ((128*FM_QS + 64*FM_KS + 64*FM_VS) * 4)

__global__ __launch_bounds__(256, 2)
void flash_mma(const float* __restrict__ Q, const float* __restrict__ K,
               const float* __restrict__ V, float* __restrict__ O)
{
    extern __shared__ uint32_t smu[];
    uint32_t* qp  = smu;
    uint32_t* ksm = smu + 128*FM_QS;
    uint32_t* vsm = ksm + 64*FM_KS;

    const int qt = gridDim.x - 1 - blockIdx.x;   // heavy tiles launch first
    const int h = blockIdx.y, b = blockIdx.z;
    const int kh = h >> 2;
    const int tid  = threadIdx.x;
    const int lane = tid & 31, warp = tid >> 5;
    const int m0 = warp * 16;
    const int lr = lane >> 2, lc = lane & 3;
    const float scale = 0.125f;

    const size_t qrow0 = (size_t)(b*SEQ) + qt*128;

    // Q tile -> smem (tf32): 128 rows x 16 float4 chunks (8 passes)
    #pragma unroll
    for (int e = tid; e < 128*16; e += 256) {
        int r = e >> 4, c4 = (e & 15) * 4;
        float4 v4 = *(const float4*)(Q + (qrow0 + r)*D_MODEL + h*HD + c4);
        *(uint4*)(qp + r*FM_QS + c4) =
            make_uint4(f2tf32(v4.x), f2tf32(v4.y), f2tf32(v4.z), f2tf32(v4.w));
    }
    __syncthreads();

    uint32_t qa[8][4];
    #pragma unroll
    for (int ks = 0; ks < 8; ks++) {
        int kb = ks * 8;
        qa[ks][0] = qp[(m0+lr  )*FM_QS + kb + lc];
        qa[ks][1] = qp[(m0+lr+8)*FM_QS + kb + lc];
        qa[ks][2] = qp[(m0+lr  )*FM_QS + kb + lc + 4];
        qa[ks][3] = qp[(m0+lr+8)*FM_QS + kb + lc + 4];
    }

    float o[8][4];
    #pragma unroll
    for (int nt = 0; nt < 8; nt++)
        #pragma unroll
        for (int e = 0; e < 4; e++) o[nt][e] = 0.f;
    float mrow0 = -INFINITY, mrow1 = -INFINITY, lrow0 = 0.f, lrow1 = 0.f;

    const int ktmax = 2*qt + 1;
    for (int kt = 0; kt <= ktmax; kt++) {
        // K,V tiles -> smem (tf32): 64 rows x 16 chunks (4 passes)
        #pragma unroll
        for (int e = tid; e < 64*16; e += 256) {
            int r = e >> 4, c4 = (e & 15) * 4;
            size_t gi = ((size_t)(b*SEQ) + kt*64 + r) * KVW + kh*HD + c4;
            float4 kv = *(const float4*)(K + gi);
            float4 vv = *(const float4*)(V + gi);
            *(uint4*)(ksm + r*FM_KS + c4) =
                make_uint4(f2tf32(kv.x), f2tf32(kv.y), f2tf32(kv.z), f2tf32(kv.w));
            *(uint4*)(vsm + r*FM_VS + c4) =
                make_uint4(f2tf32(vv.x), f2tf32(vv.y), f2tf32(vv.z), f2tf32(vv.w));
        }
        __syncthreads();

        float s[8][4];
        #pragma unroll
        for (int nt = 0; nt < 8; nt++)
            #pragma unroll
            for (int e = 0; e < 4; e++) s[nt][e] = 0.f;

        #pragma unroll
        for (int ks = 0; ks < 8; ks++) {
            int kb = ks * 8;
            uint32_t bf[8][2];
            #pragma unroll
            for (int nt = 0; nt < 8; nt++) {
                bf[nt][0] = ksm[(nt*8 + lr)*FM_KS + kb + lc];
                bf[nt][1] = ksm[(nt*8 + lr)*FM_KS + kb + lc + 4];
            }
            #pragma unroll
            for (int nt = 0; nt < 8; nt++)
                MMA_TF32(s[nt], qa[ks], bf[nt]);
        }

        const bool part = (kt >= 2*qt);
        const int rg0 = qt*128 + m0 + lr;
        const int rg1 = rg0 + 8;
        #pragma unroll
        for (int nt = 0; nt < 8; nt++) {
            int cg = kt*64 + nt*8 + 2*lc;
            s[nt][0] *= scale; s[nt][1] *= scale;
            s[nt][2] *= scale; s[nt][3] *= scale;
            if (part) {
                if (cg     > rg0) s[nt][0] = -INFINITY;
                if (cg + 1 > rg0) s[nt][1] = -INFINITY;
                if (cg     > rg1) s[nt][2] = -INFINITY;
                if (cg + 1 > rg1) s[nt][3] = -INFINITY;
            }
        }

        float mx0 = -INFINITY, mx1 = -INFINITY;
        #pragma unroll
        for (int nt = 0; nt < 8; nt++) {
            mx0 = fmaxf(mx0, fmaxf(s[nt][0], s[nt][1]));
            mx1 = fmaxf(mx1, fmaxf(s[nt][2], s[nt][3]));
        }
        mx0 = fmaxf(mx0, __shfl_xor_sync(0xffffffffu, mx0, 1));
        mx0 = fmaxf(mx0, __shfl_xor_sync(0xffffffffu, mx0, 2));
        mx1 = fmaxf(mx1, __shfl_xor_sync(0xffffffffu, mx1, 1));
        mx1 = fmaxf(mx1, __shfl_xor_sync(0xffffffffu, mx1, 2));

        float mn0 = fmaxf(mrow0, mx0), mn1 = fmaxf(mrow1, mx1);
        float al0 = __expf(mrow0 - mn0), al1 = __expf(mrow1 - mn1);
        float rs0 = 0.f, rs1 = 0.f;
        #pragma unroll
        for (int nt = 0; nt < 8; nt++) {
            s[nt][0] = __expf(s[nt][0] - mn0); rs0 += s[nt][0];
            s[nt][1] = __expf(s[nt][1] - mn0); rs0 += s[nt][1];
            s[nt][2] = __expf(s[nt][2] - mn1); rs1 += s[nt][2];
            s[nt][3] = __expf(s[nt][3] - mn1); rs1 += s[nt][3];
        }
        rs0 += __shfl_xor_sync(0xffffffffu, rs0, 1);
        rs0 += __shfl_xor_sync(0xffffffffu, rs0, 2);
        rs1 += __shfl_xor_sync(0xffffffffu, rs1, 1);
        rs1 += __shfl_xor_sync(0xffffffffu, rs1, 2);
        lrow0 = lrow0 * al0 + rs0; mrow0 = mn0;
        lrow1 = lrow1 * al1 + rs1; mrow1 = mn1;

        #pragma unroll
        for (int nt = 0; nt < 8; nt++) {
            o[nt][0] *= al0; o[nt][1] *= al0;
            o[nt][2] *= al1; o[nt][3] *= al1;
        }

        #pragma unroll
        for (int nt = 0; nt < 8; nt++) {
            uint32_t* p0 = qp + (m0+lr  )*FM_QS + nt*8 + 2*lc;
            uint32_t* p1 = qp + (m0+lr+8)*FM_QS + nt*8 + 2*lc;
            p0[0] = f2tf32(s[nt][0]); p0[1] = f2tf32(s[nt][1]);
            p1[0] = f2tf32(s[nt][2]); p1[1] = f2tf32(s[nt][3]);
        }

        #pragma unroll
        for (int ks = 0; ks < 8; ks++) {
            int kb = ks * 8;
            uint32_t pa[4];
            pa[0] = qp[(m0+lr  )*FM_QS + kb + lc];
            pa[1] = qp[(m0+lr+8)*FM_QS + kb + lc];
            pa[2] = qp[(m0+lr  )*FM_QS + kb + lc + 4];
            pa[3] = qp[(m0+lr+8)*FM_QS + kb + lc + 4];
            uint32_t bf[8][2];
            #pragma unroll
            for (int nt = 0; nt < 8; nt++) {
                bf[nt][0] = vsm[(kb + lc    )*FM_VS + nt*8 + lr];
                bf[nt][1] = vsm[(kb + lc + 4)*FM_VS + nt*8 + lr];
            }
            #pragma unroll
            for (int nt = 0; nt < 8; nt++)
                MMA_TF32(o[nt], pa, bf[nt]);
        }
        __syncthreads();
    }

    float inv0 = 1.f / lrow0, inv1 = 1.f / lrow1;
    #pragma unroll
    for (int nt = 0; nt < 8; nt++) {
        int cc = h*HD + nt*8 + 2*lc;
        *(float2*)(O + (qrow0 + m0 + lr    )*D_MODEL + cc) =
            make_float2(o[nt][0]*inv0, o[nt][1]*inv0);
        *(float2*)(O + (qrow0 + m0 + lr + 8)*D_MODEL + cc) =
            make_float2(o[nt][2]*inv1, o[nt][3]*inv1);
    }
}

// ---------------------------------------------------------------------------
extern "C" void kernel_launch(void* const* d_in, const int* in_sizes, int n_in,
                              void* d_out, int out_size)
{
    (void)in_sizes; (void)n_in; (void)out_size;
    const float* x  = (const float*)d_in[0];
    const float* wq = (const float*)d_in[1];
    const float* wk = (const float*)d_in[2];
    const float* wv = (const float*)d_in[3];
    const float* wo = (const float*)d_in[4];
    float* out = (float*)d_out;

    float *q, *k, *v, *attn;
    cudaGetSymbolAddress((void**)&q,    g_q);
    cudaGetSymbolAddress((void**)&k,    g_k);
    cudaGetSymbolAddress((void**)&v,    g_v);
    cudaGetSymbolAddress((void**)&attn, g_attn);

    cudaFuncSetAttribute(flash_mma, cudaFuncAttributeMaxDynamicSharedMemorySize, FM_SMEM);
    cudaFuncSetAttribute(gemm_qkv,  cudaFuncAttributeMaxDynamicSharedMemorySize, GP_SMEM);
    cudaFuncSetAttribute(gemm_tf32p,cudaFuncAttributeMaxDynamicSharedMemorySize, GP_SMEM);

    // fused q/k/v projections (pipelined tf32)
    gemm_qkv<<<dim3(24, MROWS/128), 256, GP_SMEM>>>(x, wq, wk, wv, q, k, v);
    // sign-flipped interleaved rope
    rope_kernel<<<(MROWS*(D_MODEL/2) + 255)/256, 256>>>(q, D_MODEL);
    rope_kernel<<<(MROWS*(KVW/2)    + 255)/256, 256>>>(k, KVW);
    // attention (tf32 tensor cores)
    flash_mma<<<dim3(SEQ/128, NH, NBATCH), 256, FM_SMEM>>>(q, k, v, attn);
    // output projection (pipelined tf32)
    gemm_tf32p<<<dim3(D_MODEL/128, MROWS/128), 256, GP_SMEM>>>(attn, wo, out, D_MODEL, D_MODEL);
}

// round 15
// speedup vs baseline: 1.1387x; 1.1387x over previous
#include <cuda_runtime.h>
#include <math.h>
#include <stdint.h>

#define D_MODEL 2048
#define SEQ     2048
#define NBATCH  2
#define NH      32
#define NKV     8
#define HD      64
#define NREP    4
#define KVW     (NKV*HD)        // 512
#define MROWS   (NBATCH*SEQ)    // 4096

// scratch (static device globals — no allocations allowed)
__device__ float    g_q[(size_t)MROWS * D_MODEL];
__device__ float    g_k[(size_t)MROWS * KVW];
__device__ float    g_v[(size_t)MROWS * KVW];
__device__ uint32_t g_attn_t[(size_t)MROWS * D_MODEL];   // tf32 bits
// preconverted tf32 operands
__device__ uint32_t g_xt [(size_t)MROWS   * D_MODEL];
__device__ uint32_t g_wqt[(size_t)D_MODEL * D_MODEL];
__device__ uint32_t g_wkt[(size_t)KVW     * D_MODEL];
__device__ uint32_t g_wvt[(size_t)KVW     * D_MODEL];
__device__ uint32_t g_wot[(size_t)D_MODEL * D_MODEL];

__device__ __forceinline__ uint32_t f2tf32(float x) {
    uint32_t r;
    asm("cvt.rna.tf32.f32 %0, %1;" : "=r"(r) : "f"(x));
    return r;
}

#define MMA_TF32(C, A, B)                                                     \
    asm volatile(                                                             \
        "mma.sync.aligned.m16n8k8.row.col.f32.tf32.tf32.f32 "                \
        "{%0,%1,%2,%3}, {%4,%5,%6,%7}, {%8,%9}, {%0,%1,%2,%3};"              \
        : "+f"((C)[0]), "+f"((C)[1]), "+f"((C)[2]), "+f"((C)[3])             \
        : "r"((A)[0]), "r"((A)[1]), "r"((A)[2]), "r"((A)[3]),                \
          "r"((B)[0]), "r"((B)[1]))

__device__ __forceinline__ void cp_async16(uint32_t* smem_dst, const void* gsrc) {
    uint32_t s = (uint32_t)__cvta_generic_to_shared(smem_dst);
    asm volatile("cp.async.cg.shared.global [%0], [%1], 16;\n"
                 :: "r"(s), "l"(gsrc));
}
#define CP_COMMIT() asm volatile("cp.async.commit_group;\n")
#define CP_WAIT1()  asm volatile("cp.async.wait_group 1;\n")

// ---------------------------------------------------------------------------
// tf32 pre-conversion: out[i] = cvt.rna.tf32(in[i])   (n % 4 == 0)
// ---------------------------------------------------------------------------
__global__ void cvt_tf32_kernel(const float* __restrict__ in,
                                uint32_t* __restrict__ out, int n)
{
    int i = (blockIdx.x * blockDim.x + threadIdx.x) * 4;
    if (i >= n) return;
    float4 v = *(const float4*)(in + i);
    *(uint4*)(out + i) = make_uint4(f2tf32(v.x), f2tf32(v.y),
                                    f2tf32(v.z), f2tf32(v.w));
}

// ---------------------------------------------------------------------------
// Pipelined tf32 GEMM core: 3-stage cp.async, BK=32, ONE sync per iteration.
// Inputs are PRE-CONVERTED tf32 bits (no cvt in loop).
// C[128][128 block] = Ab[128][K] @ Bb[128][K]^T, 256 thr, 8 warps (2m x 4n).
// Hazards: issue(it+2) targets stage (it-1)%3, placed AFTER the sync that
// guarantees all warps finished compute(it-1).  wait_group 1 at iter top
// leaves {g_it, g_it+1} pending -> tile `it` has landed.
// ---------------------------------------------------------------------------
#define G3_STRIDE 36
#define G3_STAGE  (128*G3_STRIDE)
#define G3_SMEM   (3*G3_STAGE*2*4)       // 110592 bytes

__device__ __forceinline__ void gemm3_core(
    const uint32_t* __restrict__ Ab, const uint32_t* __restrict__ Bb,
    float* __restrict__ C, int N, int cx, int cy, int K)
{
    extern __shared__ uint32_t smp[];
    uint32_t* As = smp;                        // [3][128][36]
    uint32_t* Bs = smp + 3*G3_STAGE;

    const int tid  = threadIdx.x;
    const int lane = tid & 31, warp = tid >> 5;
    const int wm = (warp & 1) * 64, wn = (warp >> 1) * 32;
    const int lr = lane >> 2,  lc = lane & 3;

    float acc[4][4][4];
    #pragma unroll
    for (int mt = 0; mt < 4; mt++)
        #pragma unroll
        for (int nt = 0; nt < 4; nt++)
            #pragma unroll
            for (int e = 0; e < 4; e++) acc[mt][nt][e] = 0.f;

    // tile = 32 k-cols = 8 float4 chunks/row; 1024 chunks/matrix; 4/thread
    #define G3_ISSUE(tile, stage)                                             \
        do {                                                                  \
            _Pragma("unroll")                                                 \
            for (int i = 0; i < 4; i++) {                                     \
                int ch  = tid + i*256;                                        \
                int row = ch >> 3, kc = (ch & 7) * 4;                         \
                cp_async16(As + (stage)*G3_STAGE + row*G3_STRIDE + kc,        \
                           Ab + (size_t)row*K + (tile)*32 + kc);              \
                cp_async16(Bs + (stage)*G3_STAGE + row*G3_STRIDE + kc,        \
                           Bb + (size_t)row*K + (tile)*32 + kc);              \
            }                                                                 \
        } while (0)

    G3_ISSUE(0, 0); CP_COMMIT();
    G3_ISSUE(1, 1); CP_COMMIT();

    const int niter = K / 32;
    int stage = 0;
    for (int it = 0; it < niter; it++) {
        CP_WAIT1();               // tile `it` landed
        __syncthreads();          // all warps done with stage (it-1)

        const uint32_t* Ac = As + stage*G3_STAGE;
        const uint32_t* Bc = Bs + stage*G3_STAGE;

        #pragma unroll
        for (int ks = 0; ks < 4; ks++) {
            const int kb = ks * 8;
            uint32_t af[4][4], bf[4][2];
            #pragma unroll
            for (int mt = 0; mt < 4; mt++) {
                int r0 = wm + mt*16 + lr;
                af[mt][0] = Ac[(r0    )*G3_STRIDE + kb + lc];
                af[mt][1] = Ac[(r0 + 8)*G3_STRIDE + kb + lc];
                af[mt][2] = Ac[(r0    )*G3_STRIDE + kb + lc + 4];
                af[mt][3] = Ac[(r0 + 8)*G3_STRIDE + kb + lc + 4];
            }
            #pragma unroll
            for (int nt = 0; nt < 4; nt++) {
                int n0 = wn + nt*8 + lr;
                bf[nt][0] = Bc[n0*G3_STRIDE + kb + lc];
                bf[nt][1] = Bc[n0*G3_STRIDE + kb + lc + 4];
            }
            #pragma unroll
            for (int mt = 0; mt < 4; mt++)
                #pragma unroll
                for (int nt = 0; nt < 4; nt++)
                    MMA_TF32(acc[mt][nt], af[mt], bf[nt]);
        }

        if (it + 2 < niter) {
            int st2 = stage + 2; if (st2 >= 3) st2 -= 3;
            G3_ISSUE(it + 2, st2);
        }
        CP_COMMIT();
        stage = (stage == 2) ? 0 : stage + 1;
    }

    #pragma unroll
    for (int mt = 0; mt < 4; mt++) {
        int r0 = cy + wm + mt*16 + lr;
        #pragma unroll
        for (int nt = 0; nt < 4; nt++) {
            int cc = cx + wn + nt*8 + lc*2;
            *(float2*)(C + (size_t)r0 * N + cc) =
                make_float2(acc[mt][nt][0], acc[mt][nt][1]);
            *(float2*)(C + (size_t)(r0 + 8) * N + cc) =
                make_float2(acc[mt][nt][2], acc[mt][nt][3]);
        }
    }
    #undef G3_ISSUE
}

// Fused q/k/v projections: grid (24, MROWS/128).  bx<16 -> q, <20 -> k, else v
__global__ __launch_bounds__(256, 2)
void gemm_qkv(const uint32_t* __restrict__ xt,
              const uint32_t* __restrict__ wqt, const uint32_t* __restrict__ wkt,
              const uint32_t* __restrict__ wvt,
              float* __restrict__ q, float* __restrict__ k, float* __restrict__ v)
{
    const int bx = blockIdx.x, by = blockIdx.y;
    const uint32_t* Ab = xt + (size_t)by * 128 * D_MODEL;
    const uint32_t* Bb; float* C; int N, cx;
    if (bx < 16)      { Bb = wqt + (size_t)bx*128*D_MODEL;      C = q; N = D_MODEL; cx = bx*128; }
    else if (bx < 20) { Bb = wkt + (size_t)(bx-16)*128*D_MODEL; C = k; N = KVW;     cx = (bx-16)*128; }
    else              { Bb = wvt + (size_t)(bx-20)*128*D_MODEL; C = v; N = KVW;     cx = (bx-20)*128; }
    gemm3_core(Ab, Bb, C, N, cx, by*128, D_MODEL);
}

// Output projection: out = attn_t @ wot^T
__global__ __launch_bounds__(256, 2)
void gemm_out(const uint32_t* __restrict__ At, const uint32_t* __restrict__ Bt,
              float* __restrict__ C, int N, int K)
{
    gemm3_core(At + (size_t)blockIdx.y*128*K, Bt + (size_t)blockIdx.x*128*K,
               C, N, blockIdx.x*128, blockIdx.y*128, K);
}

// ---------------------------------------------------------------------------
// SIGN-FLIPPED interleaved RoPE (rotation by -theta), in-place.  [VERIFIED]
// ---------------------------------------------------------------------------
__global__ void rope_kernel(float* __restrict__ buf, int width)
{
    int idx = blockIdx.x * blockDim.x + threadIdx.x;
    int ppr = width >> 1;
    if (idx >= MROWS * ppr) return;
    int m = idx / ppr;
    int p = idx - m * ppr;
    int i = p & 31;
    int s = m & (SEQ - 1);
    float inv = powf(10000.0f, -((float)(2*i)) / 64.0f);
    float ang = (float)s * inv;
    float c, sn;
    sincosf(ang, &c, &sn);
    sn = -sn;
    float* el = buf + (size_t)m * width + 2*p;
    float xr = el[0], xi = el[1];
    el[0] = xr * c - xi * sn;
    el[1] = xr * sn + xi * c;
}

// ---------------------------------------------------------------------------
// Tensor-core flash attention (tf32 MMA), causal, GQA.  [R13, measured 346us]
// Epilogue writes tf32 bits (only consumer is the wo GEMM; f2tf32 idempotent).
// ---------------------------------------------------------------------------
#define FM_QS 68
#define FM_KS 68
#define FM_VS 72
#define FM_SMEM ((128*FM_QS + 64*FM_KS + 64*FM_VS) * 4)

__global__ __launch_bounds__(256, 2)
void flash_mma(const float* __restrict__ Q, const float* __restrict__ K,
               const float* __restrict__ V, uint32_t* __restrict__ Ot)
{
    extern __shared__ uint32_t smu[];
    uint32_t* qp  = smu;
    uint32_t* ksm = smu + 128*FM_QS;
    uint32_t* vsm = ksm + 64*FM_KS;

    const int qt = gridDim.x - 1 - blockIdx.x;   // heavy tiles launch first
    const int h = blockIdx.y, b = blockIdx.z;
    const int kh = h >> 2;
    const int tid  = threadIdx.x;
    const int lane = tid & 31, warp = tid >> 5;
    const int m0 = warp * 16;
    const int lr = lane >> 2, lc = lane & 3;
    const float scale = 0.125f;

    const size_t qrow0 = (size_t)(b*SEQ) + qt*128;

    #pragma unroll
    for (int e = tid; e < 128*16; e += 256) {
        int r = e >> 4, c4 = (e & 15) * 4;
        float4 v4 = *(const float4*)(Q + (qrow0 + r)*D_MODEL + h*HD + c4);
        *(uint4*)(qp + r*FM_QS + c4) =
            make_uint4(f2tf32(v4.x), f2tf32(v4.y), f2tf32(v4.z), f2tf32(v4.w));
    }
    __syncthreads();

    uint32_t qa[8][4];
    #pragma unroll
    for (int ks = 0; ks < 8; ks++) {
        int kb = ks * 8;
        qa[ks][0] = qp[(m0+lr  )*FM_QS + kb + lc];
        qa[ks][1] = qp[(m0+lr+8)*FM_QS + kb + lc];
        qa[ks][2] = qp[(m0+lr  )*FM_QS + kb + lc + 4];
        qa[ks][3] = qp[(m0+lr+8)*FM_QS + kb + lc + 4];
    }

    float o[8][4];
    #pragma unroll
    for (int nt = 0; nt < 8; nt++)
        #pragma unroll
        for (int e = 0; e < 4; e++) o[nt][e] = 0.f;
    float mrow0 = -INFINITY, mrow1 = -INFINITY, lrow0 = 0.f, lrow1 = 0.f;

    const int ktmax = 2*qt + 1;
    for (int kt = 0; kt <= ktmax; kt++) {
        #pragma unroll
        for (int e = tid; e < 64*16; e += 256) {
            int r = e >> 4, c4 = (e & 15) * 4;
            size_t gi = ((size_t)(b*SEQ) + kt*64 + r) * KVW + kh*HD + c4;
            float4 kv = *(const float4*)(K + gi);
            float4 vv = *(const float4*)(V + gi);
            *(uint4*)(ksm + r*FM_KS + c4) =
                make_uint4(f2tf32(kv.x), f2tf32(kv.y), f2tf32(kv.z), f2tf32(kv.w));
            *(uint4*)(vsm + r*FM_VS + c4) =
                make_uint4(f2tf32(vv.x), f2tf32(vv.y), f2tf32(vv.z), f2tf32(vv.w));
        }
        __syncthreads();

        float s[8][4];
        #pragma unroll
        for (int nt = 0; nt < 8; nt++)
            #pragma unroll
            for (int e = 0; e < 4; e++) s[nt][e] = 0.f;

        #pragma unroll
        for (int ks = 0; ks < 8; ks++) {
            int kb = ks * 8;
            uint32_t bf[8][2];
            #pragma unroll
            for (int nt = 0; nt < 8; nt++) {
                bf[nt][0] = ksm[(nt*8 + lr)*FM_KS + kb + lc];
                bf[nt][1] = ksm[(nt*8 + lr)*FM_KS + kb + lc + 4];
            }
            #pragma unroll
            for (int nt = 0; nt < 8; nt++)
                MMA_TF32(s[nt], qa[ks], bf[nt]);
        }

        const bool part = (kt >= 2*qt);
        const int rg0 = qt*128 + m0 + lr;
        const int rg1 = rg0 + 8;
        #pragma unroll
        for (int nt = 0; nt < 8; nt++) {
            int cg = kt*64 + nt*8 + 2*lc;
            s[nt][0] *= scale; s[nt][1] *= scale;
            s[nt][2] *= scale; s[nt][3] *= scale;
            if (part) {
                if (cg     > rg0) s[nt][0] = -INFINITY;
                if (cg + 1 > rg0) s[nt][1] = -INFINITY;
                if (cg     > rg1) s[nt][2] = -INFINITY;
                if (cg + 1 > rg1) s[nt][3] = -INFINITY;
            }
        }

        float mx0 = -INFINITY, mx1 = -INFINITY;
        #pragma unroll
        for (int nt = 0; nt < 8; nt++) {
            mx0 = fmaxf(mx0, fmaxf(s[nt][0], s[nt][1]));
            mx1 = fmaxf(mx1, fmaxf(s[nt][2], s[nt][3]));
        }
        mx0 = fmaxf(mx0, __shfl_xor_sync(0xffffffffu, mx0, 1));
        mx0 = fmaxf(mx0, __shfl_xor_sync(0xffffffffu, mx0, 2));
        mx1 = fmaxf(mx1, __shfl_xor_sync(0xffffffffu, mx1, 1));
        mx1 = fmaxf(mx1, __shfl_xor_sync(0xffffffffu, mx1, 2));

        float mn0 = fmaxf(mrow0, mx0), mn1 = fmaxf(mrow1, mx1);
        float al0 = __expf(mrow0 - mn0), al1 = __expf(mrow1 - mn1);
        float rs0 = 0.f, rs1 = 0.f;
        #pragma unroll
        for (int nt = 0; nt < 8; nt++) {
            s[nt][0] = __expf(s[nt][0] - mn0); rs0 += s[nt][0];
            s[nt][1] = __expf(s[nt][1] - mn0); rs0 += s[nt][1];
            s[nt][2] = __expf(s[nt][2] - mn1); rs1 += s[nt][2];
            s[nt][3] = __expf(s[nt][3] - mn1); rs1 += s[nt][3];
        }
        rs0 += __shfl_xor_sync(0xffffffffu, rs0, 1);
        rs0 += __shfl_xor_sync(0xffffffffu, rs0, 2);
        rs1 += __shfl_xor_sync(0xffffffffu, rs1, 1);
        rs1 += __shfl_xor_sync(0xffffffffu, rs1, 2);
        lrow0 = lrow0 * al0 + rs0; mrow0 = mn0;
        lrow1 = lrow1 * al1 + rs1; mrow1 = mn1;

        #pragma unroll
        for (int nt = 0; nt < 8; nt++) {
            o[nt][0] *= al0; o[nt][1] *= al0;
            o[nt][2] *= al1; o[nt][3] *= al1;
        }

        #pragma unroll
        for (int nt = 0; nt < 8; nt++) {
            uint32_t* p0 = qp + (m0+lr  )*FM_QS + nt*8 + 2*lc;
            uint32_t* p1 = qp + (m0+lr+8)*FM_QS + nt*8 + 2*lc;
            p0[0] = f2tf32(s[nt][0]); p0[1] = f2tf32(s[nt][1]);
            p1[0] = f2tf32(s[nt][2]); p1[1] = f2tf32(s[nt][3]);
        }

        #pragma unroll
        for (int ks = 0; ks < 8; ks++) {
            int kb = ks * 8;
            uint32_t pa[4];
            pa[0] = qp[(m0+lr  )*FM_QS + kb + lc];
            pa[1] = qp[(m0+lr+8)*FM_QS + kb + lc];
            pa[2] = qp[(m0+lr  )*FM_QS + kb + lc + 4];
            pa[3] = qp[(m0+lr+8)*FM_QS + kb + lc + 4];
            uint32_t bf[8][2];
            #pragma unroll
            for (int nt = 0; nt < 8; nt++) {
                bf[nt][0] = vsm[(kb + lc    )*FM_VS + nt*8 + lr];
                bf[nt][1] = vsm[(kb + lc + 4)*FM_VS + nt*8 + lr];
            }
            #pragma unroll
            for (int nt = 0; nt < 8; nt++)
                MMA_TF32(o[nt], pa, bf[nt]);
        }
        __syncthreads();
    }

    float inv0 = 1.f / lrow0, inv1 = 1.f / lrow1;
    #pragma unroll
    for (int nt = 0; nt < 8; nt++) {
        int cc = h*HD + nt*8 + 2*lc;
        *(uint2*)(Ot + (qrow0 + m0 + lr    )*D_MODEL + cc) =
            make_uint2(f2tf32(o[nt][0]*inv0), f2tf32(o[nt][1]*inv0));
        *(uint2*)(Ot + (qrow0 + m0 + lr + 8)*D_MODEL + cc) =
            make_uint2(f2tf32(o[nt][2]*inv1), f2tf32(o[nt][3]*inv1));
    }
}

// ---------------------------------------------------------------------------
extern "C" void kernel_launch(void* const* d_in, const int* in_sizes, int n_in,
                              void* d_out, int out_size)
{
    (void)in_sizes; (void)n_in; (void)out_size;
    const float* x  = (const float*)d_in[0];
    const float* wq = (const float*)d_in[1];
    const float* wk = (const float*)d_in[2];
    const float* wv = (const float*)d_in[3];
    const float* wo = (const float*)d_in[4];
    float* out = (float*)d_out;

    float *q, *k, *v;
    uint32_t *attn_t, *xt, *wqt, *wkt, *wvt, *wot;
    cudaGetSymbolAddress((void**)&q,      g_q);
    cudaGetSymbolAddress((void**)&k,      g_k);
    cudaGetSymbolAddress((void**)&v,      g_v);
    cudaGetSymbolAddress((void**)&attn_t, g_attn_t);
    cudaGetSymbolAddress((void**)&xt,     g_xt);
    cudaGetSymbolAddress((void**)&wqt,    g_wqt);
    cudaGetSymbolAddress((void**)&wkt,    g_wkt);
    cudaGetSymbolAddress((void**)&wvt,    g_wvt);
    cudaGetSymbolAddress((void**)&wot,    g_wot);

    cudaFuncSetAttribute(flash_mma, cudaFuncAttributeMaxDynamicSharedMemorySize, FM_SMEM);
    cudaFuncSetAttribute(gemm_qkv,  cudaFuncAttributeMaxDynamicSharedMemorySize, G3_SMEM);
    cudaFuncSetAttribute(gemm_out,  cudaFuncAttributeMaxDynamicSharedMemorySize, G3_SMEM);

    // tf32 pre-conversion (cvt.rna — identical rounding to in-loop path)
    {
        const int nx  = MROWS   * D_MODEL;
        const int nwq = D_MODEL * D_MODEL;
        const int nwk = KVW     * D_MODEL;
        cvt_tf32_kernel<<<nx /4/256, 256>>>(x,  xt,  nx);
        cvt_tf32_kernel<<<nwq/4/256, 256>>>(wq, wqt, nwq);
        cvt_tf32_kernel<<<nwk/4/256, 256>>>(wk, wkt, nwk);
        cvt_tf32_kernel<<<nwk/4/256, 256>>>(wv, wvt, nwk);
        cvt_tf32_kernel<<<nwq/4/256, 256>>>(wo, wot, nwq);
    }

    // fused q/k/v projections (3-stage pipelined tf32)
    gemm_qkv<<<dim3(24, MROWS/128), 256, G3_SMEM>>>(xt, wqt, wkt, wvt, q, k, v);
    // sign-flipped interleaved rope
    rope_kernel<<<(MROWS*(D_MODEL/2) + 255)/256, 256>>>(q, D_MODEL);
    rope_kernel<<<(MROWS*(KVW/2)    + 255)/256, 256>>>(k, KVW);
    // attention (tf32 tensor cores) — writes tf32 bits
    flash_mma<<<dim3(SEQ/128, NH, NBATCH), 256, FM_SMEM>>>(q, k, v, attn_t);
    // output projection
    gemm_out<<<dim3(D_MODEL/128, MROWS/128), 256, G3_SMEM>>>(attn_t, wot, out, D_MODEL, D_MODEL);
}

// round 16
// speedup vs baseline: 1.1948x; 1.0492x over previous
#include <cuda_runtime.h>
#include <math.h>
#include <stdint.h>

#define D_MODEL 2048
#define SEQ     2048
#define NBATCH  2
#define NH      32
#define NKV     8
#define HD      64
#define NREP    4
#define KVW     (NKV*HD)        // 512
#define MROWS   (NBATCH*SEQ)    // 4096

// scratch (static device globals — no allocations allowed)
__device__ uint32_t g_q[(size_t)MROWS * D_MODEL];        // tf32 bits, rope applied
__device__ uint32_t g_k[(size_t)MROWS * KVW];            // tf32 bits, rope applied
__device__ uint32_t g_v[(size_t)MROWS * KVW];            // tf32 bits
__device__ uint32_t g_attn_t[(size_t)MROWS * D_MODEL];   // tf32 bits
// preconverted tf32 operands
__device__ uint32_t g_xt [(size_t)MROWS   * D_MODEL];
__device__ uint32_t g_wqt[(size_t)D_MODEL * D_MODEL];
__device__ uint32_t g_wkt[(size_t)KVW     * D_MODEL];
__device__ uint32_t g_wvt[(size_t)KVW     * D_MODEL];
__device__ uint32_t g_wot[(size_t)D_MODEL * D_MODEL];

__device__ __forceinline__ uint32_t f2tf32(float x) {
    uint32_t r;
    asm("cvt.rna.tf32.f32 %0, %1;" : "=r"(r) : "f"(x));
    return r;
}

#define MMA_TF32(C, A, B)                                                     \
    asm volatile(                                                             \
        "mma.sync.aligned.m16n8k8.row.col.f32.tf32.tf32.f32 "                \
        "{%0,%1,%2,%3}, {%4,%5,%6,%7}, {%8,%9}, {%0,%1,%2,%3};"              \
        : "+f"((C)[0]), "+f"((C)[1]), "+f"((C)[2]), "+f"((C)[3])             \
        : "r"((A)[0]), "r"((A)[1]), "r"((A)[2]), "r"((A)[3]),                \
          "r"((B)[0]), "r"((B)[1]))

__device__ __forceinline__ void cp_async16(uint32_t* smem_dst, const void* gsrc) {
    uint32_t s = (uint32_t)__cvta_generic_to_shared(smem_dst);
    asm volatile("cp.async.cg.shared.global [%0], [%1], 16;\n"
                 :: "r"(s), "l"(gsrc));
}
#define CP_COMMIT() asm volatile("cp.async.commit_group;\n")
#define CP_WAIT1()  asm volatile("cp.async.wait_group 1;\n")

// ---------------------------------------------------------------------------
// tf32 pre-conversion: out[i] = cvt.rna.tf32(in[i])   (n % 4 == 0)
// ---------------------------------------------------------------------------
__global__ void cvt_tf32_kernel(const float* __restrict__ in,
                                uint32_t* __restrict__ out, int n)
{
    int i = (blockIdx.x * blockDim.x + threadIdx.x) * 4;
    if (i >= n) return;
    float4 v = *(const float4*)(in + i);
    *(uint4*)(out + i) = make_uint4(f2tf32(v.x), f2tf32(v.y),
                                    f2tf32(v.z), f2tf32(v.w));
}

// ---------------------------------------------------------------------------
// Pipelined tf32 GEMM core: 3-stage cp.async, BK=32, ONE sync per iteration.
// MODE 0: fp32 out.  MODE 1: sign-flipped interleaved RoPE + tf32-bits out.
// MODE 2: tf32-bits out.
// ---------------------------------------------------------------------------
#define G3_STRIDE 36
#define G3_STAGE  (128*G3_STRIDE)
#define G3_SMEM   (3*G3_STAGE*2*4)       // 110592 bytes

template<int MODE>
__device__ __forceinline__ void gemm3_core(
    const uint32_t* __restrict__ Ab, const uint32_t* __restrict__ Bb,
    void* __restrict__ Cv, int N, int cx, int cy, int K)
{
    extern __shared__ uint32_t smp[];
    uint32_t* As = smp;                        // [3][128][36]
    uint32_t* Bs = smp + 3*G3_STAGE;

    const int tid  = threadIdx.x;
    const int lane = tid & 31, warp = tid >> 5;
    const int wm = (warp & 1) * 64, wn = (warp >> 1) * 32;
    const int lr = lane >> 2,  lc = lane & 3;

    float acc[4][4][4];
    #pragma unroll
    for (int mt = 0; mt < 4; mt++)
        #pragma unroll
        for (int nt = 0; nt < 4; nt++)
            #pragma unroll
            for (int e = 0; e < 4; e++) acc[mt][nt][e] = 0.f;

    #define G3_ISSUE(tile, stage)                                             \
        do {                                                                  \
            _Pragma("unroll")                                                 \
            for (int i = 0; i < 4; i++) {                                     \
                int ch  = tid + i*256;                                        \
                int row = ch >> 3, kc = (ch & 7) * 4;                         \
                cp_async16(As + (stage)*G3_STAGE + row*G3_STRIDE + kc,        \
                           Ab + (size_t)row*K + (tile)*32 + kc);              \
                cp_async16(Bs + (stage)*G3_STAGE + row*G3_STRIDE + kc,        \
                           Bb + (size_t)row*K + (tile)*32 + kc);              \
            }                                                                 \
        } while (0)

    G3_ISSUE(0, 0); CP_COMMIT();
    G3_ISSUE(1, 1); CP_COMMIT();

    const int niter = K / 32;
    int stage = 0;
    for (int it = 0; it < niter; it++) {
        CP_WAIT1();               // tile `it` landed
        __syncthreads();          // all warps done with stage (it-1)

        const uint32_t* Ac = As + stage*G3_STAGE;
        const uint32_t* Bc = Bs + stage*G3_STAGE;

        #pragma unroll
        for (int ks = 0; ks < 4; ks++) {
            const int kb = ks * 8;
            uint32_t af[4][4], bf[4][2];
            #pragma unroll
            for (int mt = 0; mt < 4; mt++) {
                int r0 = wm + mt*16 + lr;
                af[mt][0] = Ac[(r0    )*G3_STRIDE + kb + lc];
                af[mt][1] = Ac[(r0 + 8)*G3_STRIDE + kb + lc];
                af[mt][2] = Ac[(r0    )*G3_STRIDE + kb + lc + 4];
                af[mt][3] = Ac[(r0 + 8)*G3_STRIDE + kb + lc + 4];
            }
            #pragma unroll
            for (int nt = 0; nt < 4; nt++) {
                int n0 = wn + nt*8 + lr;
                bf[nt][0] = Bc[n0*G3_STRIDE + kb + lc];
                bf[nt][1] = Bc[n0*G3_STRIDE + kb + lc + 4];
            }
            #pragma unroll
            for (int mt = 0; mt < 4; mt++)
                #pragma unroll
                for (int nt = 0; nt < 4; nt++)
                    MMA_TF32(acc[mt][nt], af[mt], bf[nt]);
        }

        if (it + 2 < niter) {
            int st2 = stage + 2; if (st2 >= 3) st2 -= 3;
            G3_ISSUE(it + 2, st2);
        }
        CP_COMMIT();
        stage = (stage == 2) ? 0 : stage + 1;
    }

    if (MODE == 0) {
        float* C = (float*)Cv;
        #pragma unroll
        for (int mt = 0; mt < 4; mt++) {
            int r0 = cy + wm + mt*16 + lr;
            #pragma unroll
            for (int nt = 0; nt < 4; nt++) {
                int cc = cx + wn + nt*8 + lc*2;
                *(float2*)(C + (size_t)r0 * N + cc) =
                    make_float2(acc[mt][nt][0], acc[mt][nt][1]);
                *(float2*)(C + (size_t)(r0 + 8) * N + cc) =
                    make_float2(acc[mt][nt][2], acc[mt][nt][3]);
            }
        }
    } else if (MODE == 2) {
        uint32_t* C = (uint32_t*)Cv;
        #pragma unroll
        for (int mt = 0; mt < 4; mt++) {
            int r0 = cy + wm + mt*16 + lr;
            #pragma unroll
            for (int nt = 0; nt < 4; nt++) {
                int cc = cx + wn + nt*8 + lc*2;
                *(uint2*)(C + (size_t)r0 * N + cc) =
                    make_uint2(f2tf32(acc[mt][nt][0]), f2tf32(acc[mt][nt][1]));
                *(uint2*)(C + (size_t)(r0 + 8) * N + cc) =
                    make_uint2(f2tf32(acc[mt][nt][2]), f2tf32(acc[mt][nt][3]));
            }
        }
    } else {
        // MODE 1: rope (rotation by -theta, interleaved pairs) then tf32 bits.
        // Column pair (cc, cc+1) with cc even = one rotation pair.
        uint32_t* C = (uint32_t*)Cv;
        #pragma unroll
        for (int nt = 0; nt < 4; nt++) {
            int cc = cx + wn + nt*8 + lc*2;
            int i  = (cc & 63) >> 1;
            float inv = powf(10000.0f, -((float)(2*i)) / 64.0f);
            #pragma unroll
            for (int mt = 0; mt < 4; mt++) {
                int r0 = cy + wm + mt*16 + lr;
                float c0, s0, c1, s1;
                sincosf((float)(r0 & (SEQ-1)) * inv, &c0, &s0);      s0 = -s0;
                sincosf((float)((r0+8) & (SEQ-1)) * inv, &c1, &s1);  s1 = -s1;
                float xr0 = acc[mt][nt][0], xi0 = acc[mt][nt][1];
                float xr1 = acc[mt][nt][2], xi1 = acc[mt][nt][3];
                *(uint2*)(C + (size_t)r0 * N + cc) =
                    make_uint2(f2tf32(xr0*c0 - xi0*s0), f2tf32(xr0*s0 + xi0*c0));
                *(uint2*)(C + (size_t)(r0+8) * N + cc) =
                    make_uint2(f2tf32(xr1*c1 - xi1*s1), f2tf32(xr1*s1 + xi1*c1));
            }
        }
    }
    #undef G3_ISSUE
}

// Fused q/k/v projections + rope: grid (24, MROWS/128).
__global__ __launch_bounds__(256, 2)
void gemm_qkv(const uint32_t* __restrict__ xt,
              const uint32_t* __restrict__ wqt, const uint32_t* __restrict__ wkt,
              const uint32_t* __restrict__ wvt,
              uint32_t* __restrict__ q, uint32_t* __restrict__ k,
              uint32_t* __restrict__ v)
{
    const int bx = blockIdx.x, by = blockIdx.y;
    const uint32_t* Ab = xt + (size_t)by * 128 * D_MODEL;
    if (bx < 16) {
        gemm3_core<1>(Ab, wqt + (size_t)bx*128*D_MODEL, q, D_MODEL,
                      bx*128, by*128, D_MODEL);
    } else if (bx < 20) {
        gemm3_core<1>(Ab, wkt + (size_t)(bx-16)*128*D_MODEL, k, KVW,
                      (bx-16)*128, by*128, D_MODEL);
    } else {
        gemm3_core<2>(Ab, wvt + (size_t)(bx-20)*128*D_MODEL, v, KVW,
                      (bx-20)*128, by*128, D_MODEL);
    }
}

// Output projection: out = attn_t @ wot^T  (fp32 out)
__global__ __launch_bounds__(256, 2)
void gemm_out(const uint32_t* __restrict__ At, const uint32_t* __restrict__ Bt,
              float* __restrict__ C, int N, int K)
{
    gemm3_core<0>(At + (size_t)blockIdx.y*128*K, Bt + (size_t)blockIdx.x*128*K,
                  C, N, blockIdx.x*128, blockIdx.y*128, K);
}

// ---------------------------------------------------------------------------
// Tensor-core flash attention (tf32 MMA), causal, GQA.
// Q/K/V arrive as tf32 bits (rope pre-applied).  K/V double-buffered cp.async.
// ---------------------------------------------------------------------------
#define FM_QS 68
#define FM_KS 68
#define FM_VS 72
#define FM_KSTG (64*FM_KS)
#define FM_VSTG (64*FM_VS)
#define FM_SMEM ((128*FM_QS + 2*FM_KSTG + 2*FM_VSTG) * 4)   // 106496 bytes

__global__ __launch_bounds__(256, 2)
void flash_mma(const uint32_t* __restrict__ Qt, const uint32_t* __restrict__ Kt,
               const uint32_t* __restrict__ Vt, uint32_t* __restrict__ Ot)
{
    extern __shared__ uint32_t smu[];
    uint32_t* qp  = smu;                          // [128][68]  Q -> P
    uint32_t* ksm = smu + 128*FM_QS;              // [2][64][68]
    uint32_t* vsm = ksm + 2*FM_KSTG;              // [2][64][72]

    const int qt = gridDim.x - 1 - blockIdx.x;    // heavy tiles launch first
    const int h = blockIdx.y, b = blockIdx.z;
    const int kh = h >> 2;
    const int tid  = threadIdx.x;
    const int lane = tid & 31, warp = tid >> 5;
    const int m0 = warp * 16;
    const int lr = lane >> 2, lc = lane & 3;
    const float scale = 0.125f;

    const size_t qrow0 = (size_t)(b*SEQ) + qt*128;

    // Q tile -> smem (raw tf32 bits)
    #pragma unroll
    for (int e = tid; e < 128*16; e += 256) {
        int r = e >> 4, c4 = (e & 15) * 4;
        *(uint4*)(qp + r*FM_QS + c4) =
            *(const uint4*)(Qt + (qrow0 + r)*D_MODEL + h*HD + c4);
    }

    #define FM_ISSUE(kt_, buf_)                                               \
        do {                                                                  \
            _Pragma("unroll")                                                 \
            for (int i = 0; i < 4; i++) {                                     \
                int ch = tid + i*256;                                         \
                int r = ch >> 4, c4 = (ch & 15) * 4;                          \
                size_t gi = ((size_t)(b*SEQ) + (kt_)*64 + r) * KVW            \
                            + kh*HD + c4;                                     \
                cp_async16(ksm + (buf_)*FM_KSTG + r*FM_KS + c4, Kt + gi);     \
                cp_async16(vsm + (buf_)*FM_VSTG + r*FM_VS + c4, Vt + gi);     \
            }                                                                 \
        } while (0)

    const int ktmax = 2*qt + 1;
    FM_ISSUE(0, 0); CP_COMMIT();
    if (ktmax >= 1) FM_ISSUE(1, 1);
    CP_COMMIT();

    __syncthreads();                 // Q tile visible
    uint32_t qa[8][4];
    #pragma unroll
    for (int ks = 0; ks < 8; ks++) {
        int kb = ks * 8;
        qa[ks][0] = qp[(m0+lr  )*FM_QS + kb + lc];
        qa[ks][1] = qp[(m0+lr+8)*FM_QS + kb + lc];
        qa[ks][2] = qp[(m0+lr  )*FM_QS + kb + lc + 4];
        qa[ks][3] = qp[(m0+lr+8)*FM_QS + kb + lc + 4];
    }

    float o[8][4];
    #pragma unroll
    for (int nt = 0; nt < 8; nt++)
        #pragma unroll
        for (int e = 0; e < 4; e++) o[nt][e] = 0.f;
    float mrow0 = -INFINITY, mrow1 = -INFINITY, lrow0 = 0.f, lrow1 = 0.f;

    for (int kt = 0; kt <= ktmax; kt++) {
        CP_WAIT1();                  // tile kt landed
        __syncthreads();
        const uint32_t* kc = ksm + (kt & 1)*FM_KSTG;
        const uint32_t* vc = vsm + (kt & 1)*FM_VSTG;

        float s[8][4];
        #pragma unroll
        for (int nt = 0; nt < 8; nt++)
            #pragma unroll
            for (int e = 0; e < 4; e++) s[nt][e] = 0.f;

        #pragma unroll
        for (int ks = 0; ks < 8; ks++) {
            int kb = ks * 8;
            uint32_t bf[8][2];
            #pragma unroll
            for (int nt = 0; nt < 8; nt++) {
                bf[nt][0] = kc[(nt*8 + lr)*FM_KS + kb + lc];
                bf[nt][1] = kc[(nt*8 + lr)*FM_KS + kb + lc + 4];
            }
            #pragma unroll
            for (int nt = 0; nt < 8; nt++)
                MMA_TF32(s[nt], qa[ks], bf[nt]);
        }

        const bool part = (kt >= 2*qt);
        const int rg0 = qt*128 + m0 + lr;
        const int rg1 = rg0 + 8;
        #pragma unroll
        for (int nt = 0; nt < 8; nt++) {
            int cg = kt*64 + nt*8 + 2*lc;
            s[nt][0] *= scale; s[nt][1] *= scale;
            s[nt][2] *= scale; s[nt][3] *= scale;
            if (part) {
                if (cg     > rg0) s[nt][0] = -INFINITY;
                if (cg + 1 > rg0) s[nt][1] = -INFINITY;
                if (cg     > rg1) s[nt][2] = -INFINITY;
                if (cg + 1 > rg1) s[nt][3] = -INFINITY;
            }
        }

        float mx0 = -INFINITY, mx1 = -INFINITY;
        #pragma unroll
        for (int nt = 0; nt < 8; nt++) {
            mx0 = fmaxf(mx0, fmaxf(s[nt][0], s[nt][1]));
            mx1 = fmaxf(mx1, fmaxf(s[nt][2], s[nt][3]));
        }
        mx0 = fmaxf(mx0, __shfl_xor_sync(0xffffffffu, mx0, 1));
        mx0 = fmaxf(mx0, __shfl_xor_sync(0xffffffffu, mx0, 2));
        mx1 = fmaxf(mx1, __shfl_xor_sync(0xffffffffu, mx1, 1));
        mx1 = fmaxf(mx1, __shfl_xor_sync(0xffffffffu, mx1, 2));

        float mn0 = fmaxf(mrow0, mx0), mn1 = fmaxf(mrow1, mx1);
        float al0 = __expf(mrow0 - mn0), al1 = __expf(mrow1 - mn1);
        float rs0 = 0.f, rs1 = 0.f;
        #pragma unroll
        for (int nt = 0; nt < 8; nt++) {
            s[nt][0] = __expf(s[nt][0] - mn0); rs0 += s[nt][0];
            s[nt][1] = __expf(s[nt][1] - mn0); rs0 += s[nt][1];
            s[nt][2] = __expf(s[nt][2] - mn1); rs1 += s[nt][2];
            s[nt][3] = __expf(s[nt][3] - mn1); rs1 += s[nt][3];
        }
        rs0 += __shfl_xor_sync(0xffffffffu, rs0, 1);
        rs0 += __shfl_xor_sync(0xffffffffu, rs0, 2);
        rs1 += __shfl_xor_sync(0xffffffffu, rs1, 1);
        rs1 += __shfl_xor_sync(0xffffffffu, rs1, 2);
        lrow0 = lrow0 * al0 + rs0; mrow0 = mn0;
        lrow1 = lrow1 * al1 + rs1; mrow1 = mn1;

        #pragma unroll
        for (int nt = 0; nt < 8; nt++) {
            o[nt][0] *= al0; o[nt][1] *= al0;
            o[nt][2] *= al1; o[nt][3] *= al1;
        }

        // write P (tf32 bits) to warp-private rows of qp
        #pragma unroll
        for (int nt = 0; nt < 8; nt++) {
            uint32_t* p0 = qp + (m0+lr  )*FM_QS + nt*8 + 2*lc;
            uint32_t* p1 = qp + (m0+lr+8)*FM_QS + nt*8 + 2*lc;
            p0[0] = f2tf32(s[nt][0]); p0[1] = f2tf32(s[nt][1]);
            p1[0] = f2tf32(s[nt][2]); p1[1] = f2tf32(s[nt][3]);
        }

        // O += P @ V
        #pragma unroll
        for (int ks = 0; ks < 8; ks++) {
            int kb = ks * 8;
            uint32_t pa[4];
            pa[0] = qp[(m0+lr  )*FM_QS + kb + lc];
            pa[1] = qp[(m0+lr+8)*FM_QS + kb + lc];
            pa[2] = qp[(m0+lr  )*FM_QS + kb + lc + 4];
            pa[3] = qp[(m0+lr+8)*FM_QS + kb + lc + 4];
            uint32_t bf[8][2];
            #pragma unroll
            for (int nt = 0; nt < 8; nt++) {
                bf[nt][0] = vc[(kb + lc    )*FM_VS + nt*8 + lr];
                bf[nt][1] = vc[(kb + lc + 4)*FM_VS + nt*8 + lr];
            }
            #pragma unroll
            for (int nt = 0; nt < 8; nt++)
                MMA_TF32(o[nt], pa, bf[nt]);
        }
        __syncthreads();             // all warps done with buf kt&1

        if (kt + 2 <= ktmax) FM_ISSUE(kt + 2, kt & 1);
        CP_COMMIT();
    }

    float inv0 = 1.f / lrow0, inv1 = 1.f / lrow1;
    #pragma unroll
    for (int nt = 0; nt < 8; nt++) {
        int cc = h*HD + nt*8 + 2*lc;
        *(uint2*)(Ot + (qrow0 + m0 + lr    )*D_MODEL + cc) =
            make_uint2(f2tf32(o[nt][0]*inv0), f2tf32(o[nt][1]*inv0));
        *(uint2*)(Ot + (qrow0 + m0 + lr + 8)*D_MODEL + cc) =
            make_uint2(f2tf32(o[nt][2]*inv1), f2tf32(o[nt][3]*inv1));
    }
    #undef FM_ISSUE
}

// ---------------------------------------------------------------------------
extern "C" void kernel_launch(void* const* d_in, const int* in_sizes, int n_in,
                              void* d_out, int out_size)
{
    (void)in_sizes; (void)n_in; (void)out_size;
    const float* x  = (const float*)d_in[0];
    const float* wq = (const float*)d_in[1];
    const float* wk = (const float*)d_in[2];
    const float* wv = (const float*)d_in[3];
    const float* wo = (const float*)d_in[4];
    float* out = (float*)d_out;

    uint32_t *q, *k, *v, *attn_t, *xt, *wqt, *wkt, *wvt, *wot;
    cudaGetSymbolAddress((void**)&q,      g_q);
    cudaGetSymbolAddress((void**)&k,      g_k);
    cudaGetSymbolAddress((void**)&v,      g_v);
    cudaGetSymbolAddress((void**)&attn_t, g_attn_t);
    cudaGetSymbolAddress((void**)&xt,     g_xt);
    cudaGetSymbolAddress((void**)&wqt,    g_wqt);
    cudaGetSymbolAddress((void**)&wkt,    g_wkt);
    cudaGetSymbolAddress((void**)&wvt,    g_wvt);
    cudaGetSymbolAddress((void**)&wot,    g_wot);

    cudaFuncSetAttribute(flash_mma, cudaFuncAttributeMaxDynamicSharedMemorySize, FM_SMEM);
    cudaFuncSetAttribute(gemm_qkv,  cudaFuncAttributeMaxDynamicSharedMemorySize, G3_SMEM);
    cudaFuncSetAttribute(gemm_out,  cudaFuncAttributeMaxDynamicSharedMemorySize, G3_SMEM);

    // tf32 pre-conversion
    {
        const int nx  = MROWS   * D_MODEL;
        const int nwq = D_MODEL * D_MODEL;
        const int nwk = KVW     * D_MODEL;
        cvt_tf32_kernel<<<nx /4/256, 256>>>(x,  xt,  nx);
        cvt_tf32_kernel<<<nwq/4/256, 256>>>(wq, wqt, nwq);
        cvt_tf32_kernel<<<nwk/4/256, 256>>>(wk, wkt, nwk);
        cvt_tf32_kernel<<<nwk/4/256, 256>>>(wv, wvt, nwk);
        cvt_tf32_kernel<<<nwq/4/256, 256>>>(wo, wot, nwq);
    }

    // fused q/k/v projections + rope (writes tf32 bits)
    gemm_qkv<<<dim3(24, MROWS/128), 256, G3_SMEM>>>(xt, wqt, wkt, wvt, q, k, v);
    // attention (tf32 tensor cores, cp.async K/V pipeline) — writes tf32 bits
    flash_mma<<<dim3(SEQ/128, NH, NBATCH), 256, FM_SMEM>>>(q, k, v, attn_t);
    // output projection
    gemm_out<<<dim3(D_MODEL/128, MROWS/128), 256, G3_SMEM>>>(attn_t, wot, out, D_MODEL, D_MODEL);
}